// round 9
// baseline (speedup 1.0000x reference)
#include <cuda_runtime.h>
#include <cuda_bf16.h>
#include <cstdint>

#define N_NODES 50000
#define NE      600000
#define D       128
#define SCAN_B  512
#define NSCANB  ((N_NODES + SCAN_B - 1) / SCAN_B)   // 98
#define CNT_BLK ((NE + 255) / 256)                   // 2344

// ---------------------------------------------------------------------------
// Scratch (static device globals — no allocations allowed)
// ---------------------------------------------------------------------------
__device__ int   g_deg[N_NODES];
__device__ float g_dinv[N_NODES];
__device__ float g_msg[(size_t)N_NODES * D];   // g[i] = dinv[i] * (x[i] @ W)
__device__ int   g_rowptr[N_NODES + 1];
__device__ int   g_cursor[N_NODES];
__device__ int   g_srcidx[NE];
__device__ int   g_blocksum[128];
// W in mma.sync B-fragment layout: [kstep 8][ntile 16][lane 32] uint2, hi & lo
__device__ uint2 g_Bhi[8 * 16 * 32];
__device__ uint2 g_Blo[8 * 16 * 32];

// ---------------------------------------------------------------------------
// bf16 helpers
// ---------------------------------------------------------------------------
__device__ __forceinline__ uint32_t bfpack(float a, float b) {
    __nv_bfloat162 h = __floats2bfloat162_rn(a, b);
    return *(uint32_t*)&h;
}
__device__ __forceinline__ uint32_t bfhi_lo(float a, float b, float& ra, float& rb) {
    __nv_bfloat162 h = __floats2bfloat162_rn(a, b);
    ra = a - __bfloat162float(h.x);
    rb = b - __bfloat162float(h.y);
    return *(uint32_t*)&h;
}

#define MMA16816(c, a0, a1, a2, a3, b0, b1)                                    \
    asm volatile(                                                              \
        "mma.sync.aligned.m16n8k16.row.col.f32.bf16.bf16.f32 "                 \
        "{%0,%1,%2,%3}, {%4,%5,%6,%7}, {%8,%9}, {%0,%1,%2,%3};"                \
        : "+f"((c)[0]), "+f"((c)[1]), "+f"((c)[2]), "+f"((c)[3])               \
        : "r"(a0), "r"(a1), "r"(a2), "r"(a3), "r"(b0), "r"(b1))

// ---------------------------------------------------------------------------
// L1: zero degree
// ---------------------------------------------------------------------------
__global__ void k_init_deg() {
    int i = blockIdx.x * blockDim.x + threadIdx.x;
    if (i < N_NODES) g_deg[i] = 0;
}

// ---------------------------------------------------------------------------
// L2 (fused): blocks [0, CNT_BLK) count in-degree; block CNT_BLK preps W frags
// ---------------------------------------------------------------------------
__global__ __launch_bounds__(256) void k_count_prep(const int* __restrict__ ei,
                                                    const float* __restrict__ W) {
    if (blockIdx.x < CNT_BLK) {
        int e = blockIdx.x * 256 + threadIdx.x;
        if (e < NE) atomicAdd(&g_deg[ei[NE + e]], 1);
        return;
    }
    for (int slot = threadIdx.x; slot < 8 * 16 * 32; slot += 256) {
        int l = slot & 31;
        int j = (slot >> 5) & 15;
        int s = slot >> 9;
        int g = l >> 2, t = l & 3;
        int n  = 8 * j + g;
        int k0 = 16 * s + 2 * t;
        float w00 = W[(k0 + 0) * D + n];
        float w01 = W[(k0 + 1) * D + n];
        float w10 = W[(k0 + 8) * D + n];
        float w11 = W[(k0 + 9) * D + n];
        float r00, r01, r10, r11;
        uint2 hi, lo;
        hi.x = bfhi_lo(w00, w01, r00, r01);
        hi.y = bfhi_lo(w10, w11, r10, r11);
        lo.x = bfpack(r00, r01);
        lo.y = bfpack(r10, r11);
        g_Bhi[slot] = hi;
        g_Blo[slot] = lo;
    }
}

// ---------------------------------------------------------------------------
// L3: block-level exclusive scan of g_deg (+ fused dinv)
// ---------------------------------------------------------------------------
__global__ __launch_bounds__(SCAN_B) void k_scan_block() {
    __shared__ int s[SCAN_B];
    int gid = blockIdx.x * SCAN_B + threadIdx.x;
    int v = (gid < N_NODES) ? g_deg[gid] : 0;
    if (gid < N_NODES) g_dinv[gid] = rsqrtf((float)(v + 1));   // fused
    s[threadIdx.x] = v;
    __syncthreads();
#pragma unroll
    for (int off = 1; off < SCAN_B; off <<= 1) {
        int t = (threadIdx.x >= off) ? s[threadIdx.x - off] : 0;
        __syncthreads();
        s[threadIdx.x] += t;
        __syncthreads();
    }
    if (gid < N_NODES) g_rowptr[gid] = s[threadIdx.x] - v;
    if (threadIdx.x == SCAN_B - 1) g_blocksum[blockIdx.x] = s[SCAN_B - 1];
}

// ---------------------------------------------------------------------------
// L5 (fused top+fix): add cross-block offsets, init cursor
// ---------------------------------------------------------------------------
__global__ __launch_bounds__(256) void k_scan_fix() {
    __shared__ int ss[128];
    int tid = threadIdx.x;
    int gid = blockIdx.x * 256 + tid;
    if (tid < 128) ss[tid] = (tid < NSCANB) ? g_blocksum[tid] : 0;
    __syncthreads();
    if (gid < N_NODES) {
        int blk = gid / SCAN_B;
        int off = 0;
        for (int i = 0; i < blk; i++) off += ss[i];
        int rp = g_rowptr[gid] + off;
        g_rowptr[gid] = rp;
        g_cursor[gid] = rp;
    }
    if (gid == 0) g_rowptr[N_NODES] = NE;
}

// L6: CSR fill
__global__ __launch_bounds__(256) void k_fill(const int* __restrict__ ei) {
    int e = blockIdx.x * blockDim.x + threadIdx.x;
    if (e >= NE) return;
    int pos = atomicAdd(&g_cursor[ei[NE + e]], 1);
    g_srcidx[pos] = ei[e];
}

// ---------------------------------------------------------------------------
// L4: GEMM via mma.sync bf16x3: g[i] = dinv[i] * (x[i] @ W)
// 128 threads / 4 warps, 64 rows per block. Warp w: rows 16w..16w+15.
// x pre-converted to packed bf16 hi/lo in smem during staging: A-frag loads
// become plain LDS.32 (stride 68 -> 4g+t bank map, conflict-free).
// ---------------------------------------------------------------------------
#define HS 68   // uint32 row stride: 68 mod 32 = 4 -> lanes hit banks 4g+t
__global__ __launch_bounds__(128) void k_gemm_mma(const float* __restrict__ x) {
    __shared__ uint32_t sHi[64 * HS];   // 17.4 KB packed bf16x2 hi
    __shared__ uint32_t sLo[64 * HS];   // 17.4 KB packed bf16x2 lo

    const int tid = threadIdx.x;
    const int w   = tid >> 5;
    const int l   = tid & 31;
    const int g   = l >> 2, t = l & 3;
    const int base = blockIdx.x * 64;

    // stage + convert x rows -> packed bf16 hi/lo
    for (int i = tid; i < 64 * 32; i += 128) {      // 32 float4 per row
        int r  = i >> 5;
        int c4 = i & 31;
        float4 v = make_float4(0.f, 0.f, 0.f, 0.f);
        if (base + r < N_NODES)
            v = ((const float4*)(x + (size_t)(base + r) * D))[c4];
        float rx, ry, rz, rw;
        uint32_t h0 = bfhi_lo(v.x, v.y, rx, ry);
        uint32_t h1 = bfhi_lo(v.z, v.w, rz, rw);
        uint32_t l0 = bfpack(rx, ry);
        uint32_t l1 = bfpack(rz, rw);
        int o = r * HS + c4 * 2;
        sHi[o] = h0; sHi[o + 1] = h1;
        sLo[o] = l0; sLo[o + 1] = l1;
    }
    __syncthreads();

    float c[16][4];
#pragma unroll
    for (int j = 0; j < 16; j++)
#pragma unroll
        for (int q = 0; q < 4; q++) c[j][q] = 0.f;

    const int r0 = 16 * w + g;
    const uint32_t* Ah  = sHi + r0 * HS;
    const uint32_t* Ah8 = Ah + 8 * HS;
    const uint32_t* Al  = sLo + r0 * HS;
    const uint32_t* Al8 = Al + 8 * HS;

#pragma unroll
    for (int s = 0; s < 8; s++) {
        int kp = 8 * s + t;
        uint32_t ah0 = Ah [kp];
        uint32_t ah1 = Ah8[kp];
        uint32_t ah2 = Ah [kp + 4];
        uint32_t ah3 = Ah8[kp + 4];
        uint32_t al0 = Al [kp];
        uint32_t al1 = Al8[kp];
        uint32_t al2 = Al [kp + 4];
        uint32_t al3 = Al8[kp + 4];

        const uint2* bh = g_Bhi + (s * 16) * 32 + l;
        const uint2* bl = g_Blo + (s * 16) * 32 + l;
#pragma unroll
        for (int j = 0; j < 16; j++) {
            uint2 B  = bh[j * 32];
            uint2 Bl = bl[j * 32];
            MMA16816(c[j], ah0, ah1, ah2, ah3, B.x,  B.y);   // hi*hi
            MMA16816(c[j], al0, al1, al2, al3, B.x,  B.y);   // lo*hi
            MMA16816(c[j], ah0, ah1, ah2, ah3, Bl.x, Bl.y);  // hi*lo
        }
    }

    int R0 = base + r0;
    int R1 = R0 + 8;
    float d0 = (R0 < N_NODES) ? g_dinv[R0] : 0.f;
    float d1 = (R1 < N_NODES) ? g_dinv[R1] : 0.f;
#pragma unroll
    for (int j = 0; j < 16; j++) {
        int col = 8 * j + 2 * t;
        if (R0 < N_NODES)
            *(float2*)(g_msg + (size_t)R0 * D + col) =
                make_float2(c[j][0] * d0, c[j][1] * d0);
        if (R1 < N_NODES)
            *(float2*)(g_msg + (size_t)R1 * D + col) =
                make_float2(c[j][2] * d1, c[j][3] * d1);
    }
}

// ---------------------------------------------------------------------------
// L7: Gather — one warp per destination node, 4-way unroll, .cg loads
// out[i] = dinv[i] * (sum_{p in CSR(i)} g[src_p] + g[i]) + b
// ---------------------------------------------------------------------------
__global__ __launch_bounds__(256) void k_gather(float* __restrict__ out,
                                                const float* __restrict__ b) {
    int w    = (blockIdx.x * 256 + threadIdx.x) >> 5;
    int lane = threadIdx.x & 31;
    if (w >= N_NODES) return;

    const float4* gm = (const float4*)g_msg;
    float4 acc = __ldcg(gm + (size_t)w * 32 + lane);   // self loop
    int p  = g_rowptr[w];
    int pe = g_rowptr[w + 1];

    for (; p + 3 < pe; p += 4) {
        int s0 = g_srcidx[p];
        int s1 = g_srcidx[p + 1];
        int s2 = g_srcidx[p + 2];
        int s3 = g_srcidx[p + 3];
        float4 a0 = __ldcg(gm + (size_t)s0 * 32 + lane);
        float4 a1 = __ldcg(gm + (size_t)s1 * 32 + lane);
        float4 a2 = __ldcg(gm + (size_t)s2 * 32 + lane);
        float4 a3 = __ldcg(gm + (size_t)s3 * 32 + lane);
        acc.x += (a0.x + a1.x) + (a2.x + a3.x);
        acc.y += (a0.y + a1.y) + (a2.y + a3.y);
        acc.z += (a0.z + a1.z) + (a2.z + a3.z);
        acc.w += (a0.w + a1.w) + (a2.w + a3.w);
    }
    for (; p < pe; p++) {
        int s0 = g_srcidx[p];
        float4 a = __ldcg(gm + (size_t)s0 * 32 + lane);
        acc.x += a.x; acc.y += a.y; acc.z += a.z; acc.w += a.w;
    }

    float dv  = g_dinv[w];
    float4 bb = ((const float4*)b)[lane];
    float4 o;
    o.x = acc.x * dv + bb.x;
    o.y = acc.y * dv + bb.y;
    o.z = acc.z * dv + bb.z;
    o.w = acc.w * dv + bb.w;
    ((float4*)out)[(size_t)w * 32 + lane] = o;
}

// ---------------------------------------------------------------------------
extern "C" void kernel_launch(void* const* d_in, const int* in_sizes, int n_in,
                              void* d_out, int out_size) {
    const float* x   = (const float*)d_in[0];
    const int*   ei  = (const int*)d_in[1];    // int32 (JAX x64-disabled)
    const float* W   = (const float*)d_in[2];
    const float* b   = (const float*)d_in[3];
    float*       out = (float*)d_out;

    k_init_deg<<<(N_NODES + 255) / 256, 256>>>();                 // 1
    k_count_prep<<<CNT_BLK + 1, 256>>>(ei, W);                    // 2
    k_scan_block<<<NSCANB, SCAN_B>>>();                           // 3
    k_gemm_mma<<<(N_NODES + 63) / 64, 128>>>(x);                  // 4 <- profiled
    k_scan_fix<<<(N_NODES + 255) / 256, 256>>>();                 // 5
    k_fill<<<(NE + 255) / 256, 256>>>(ei);                        // 6
    k_gather<<<(N_NODES * 32 + 255) / 256, 256>>>(out, b);        // 7
}